// round 1
// baseline (speedup 1.0000x reference)
#include <cuda_runtime.h>
#include <math.h>

// Problem constants (fixed by setup_inputs): B=2, S=2048, 8 blades, 4 grades.
#define S 2048
#define B 2

// Scratch for normalized q and k: [which(q=0,k=1)][b][n][blade] = 256 KB
__device__ float g_qk[2][B][S][8];

// ---------------------------------------------------------------------------
// Kernel 1: q/k = normalize(mv_linear(x, W), a)
//   q[b,n,i] = sum_m W[n,m,g(i)] * x[b,m,i], then per-grade norm scaling.
// Grid: (S rows, 2 matrices), 256 threads/block. Streams W (32 KB/row).
// ---------------------------------------------------------------------------
__global__ __launch_bounds__(256) void qk_kernel(
    const float* __restrict__ x,    // (B, S, 8)
    const float* __restrict__ Wq,   // (S, S, 4)
    const float* __restrict__ Wk,   // (S, S, 4)
    const float* __restrict__ a)    // (3000, 4)
{
    const int n     = blockIdx.x;   // output row
    const int which = blockIdx.y;   // 0 = q, 1 = k
    const int tid   = threadIdx.x;

    const float* W = which ? Wk : Wq;
    const float4* Wrow = reinterpret_cast<const float4*>(W + (size_t)n * S * 4);
    const float4* X    = reinterpret_cast<const float4*>(x);

    float acc[16];
#pragma unroll
    for (int i = 0; i < 16; i++) acc[i] = 0.f;

    // m-strided accumulation: w = (g0,g1,g2,g3) weights for (n,m)
#pragma unroll 4
    for (int m = tid; m < S; m += 256) {
        float4 w   = Wrow[m];
        float4 x0a = X[m * 2 + 0];        // b=0 blades 0..3
        float4 x0b = X[m * 2 + 1];        // b=0 blades 4..7
        float4 x1a = X[(S + m) * 2 + 0];  // b=1 blades 0..3
        float4 x1b = X[(S + m) * 2 + 1];  // b=1 blades 4..7
        acc[0]  = fmaf(w.x, x0a.x, acc[0]);
        acc[1]  = fmaf(w.y, x0a.y, acc[1]);
        acc[2]  = fmaf(w.y, x0a.z, acc[2]);
        acc[3]  = fmaf(w.y, x0a.w, acc[3]);
        acc[4]  = fmaf(w.z, x0b.x, acc[4]);
        acc[5]  = fmaf(w.z, x0b.y, acc[5]);
        acc[6]  = fmaf(w.z, x0b.z, acc[6]);
        acc[7]  = fmaf(w.w, x0b.w, acc[7]);
        acc[8]  = fmaf(w.x, x1a.x, acc[8]);
        acc[9]  = fmaf(w.y, x1a.y, acc[9]);
        acc[10] = fmaf(w.y, x1a.z, acc[10]);
        acc[11] = fmaf(w.y, x1a.w, acc[11]);
        acc[12] = fmaf(w.z, x1b.x, acc[12]);
        acc[13] = fmaf(w.z, x1b.y, acc[13]);
        acc[14] = fmaf(w.z, x1b.z, acc[14]);
        acc[15] = fmaf(w.w, x1b.w, acc[15]);
    }

    // Warp reduction of all 16 accumulators
#pragma unroll
    for (int i = 0; i < 16; i++) {
#pragma unroll
        for (int off = 16; off > 0; off >>= 1)
            acc[i] += __shfl_down_sync(0xffffffffu, acc[i], off);
    }

    __shared__ float red[8][16];
    __shared__ float vals[16];
    __shared__ float denom[B][4];
    const int warp = tid >> 5, lane = tid & 31;
    if (lane == 0) {
#pragma unroll
        for (int i = 0; i < 16; i++) red[warp][i] = acc[i];
    }
    __syncthreads();

    if (tid < 16) {
        float s = 0.f;
#pragma unroll
        for (int w2 = 0; w2 < 8; w2++) s += red[w2][tid];
        vals[tid] = s;
    }
    __syncthreads();

    if (tid < B) {
        const int b = tid;
        const float* v = &vals[b * 8];
        float nr[4];
        nr[0] = fabsf(v[0]);
        nr[1] = sqrtf(v[1] * v[1] + v[2] * v[2] + v[3] * v[3]);
        nr[2] = sqrtf(v[4] * v[4] + v[5] * v[5] + v[6] * v[6]);
        nr[3] = fabsf(v[7]);
#pragma unroll
        for (int g = 0; g < 4; g++) {
            float sa = 1.f / (1.f + expf(-a[n * 4 + g]));   // sigmoid(a[n,g])
            denom[b][g] = sa * (nr[g] - 1.f) + 1.f + 1e-6f;
        }
    }
    __syncthreads();

    if (tid < 16) {
        const int b = tid >> 3, i = tid & 7;
        const int g = (i == 0) ? 0 : (i < 4) ? 1 : (i < 7) ? 2 : 3;
        g_qk[which][b][n][i] = vals[tid] / denom[b][g];
    }
}

// ---------------------------------------------------------------------------
// Kernel 2: out[b,s,t,:] = q[b,s,:] (geometric product) k[b,t,:]
// Cl(3,0) Cayley table hardcoded: 64 signed FMAs per pair.
// Grid: (S, B), 256 threads; each thread covers 8 t's, writes 2x STG.128.
// ---------------------------------------------------------------------------
__global__ __launch_bounds__(256) void gp_kernel(float* __restrict__ out)
{
    const int s   = blockIdx.x;
    const int b   = blockIdx.y;
    const int tid = threadIdx.x;

    const float4 qa = *reinterpret_cast<const float4*>(&g_qk[0][b][s][0]);
    const float4 qb = *reinterpret_cast<const float4*>(&g_qk[0][b][s][4]);
    const float q0 = qa.x, q1 = qa.y, q2 = qa.z, q3 = qa.w;
    const float q4 = qb.x, q5 = qb.y, q6 = qb.z, q7 = qb.w;

    float4* orow = reinterpret_cast<float4*>(out + (((size_t)b * S + s) * S) * 8);
    const float4* K = reinterpret_cast<const float4*>(&g_qk[1][b][0][0]);

#pragma unroll
    for (int it = 0; it < 8; it++) {
        const int t = tid + it * 256;
        const float4 ka = K[t * 2 + 0];
        const float4 kb = K[t * 2 + 1];
        const float k0 = ka.x, k1 = ka.y, k2 = ka.z, k3 = ka.w;
        const float k4 = kb.x, k5 = kb.y, k6 = kb.z, k7 = kb.w;

        float4 o_lo, o_hi;
        o_lo.x = q0*k0 + q1*k1 + q2*k2 + q3*k3 - q4*k4 - q5*k5 - q6*k6 - q7*k7;
        o_lo.y = q0*k1 + q1*k0 - q2*k4 + q4*k2 - q3*k5 + q5*k3 - q6*k7 - q7*k6;
        o_lo.z = q0*k2 + q2*k0 + q1*k4 - q4*k1 - q3*k6 + q6*k3 + q5*k7 + q7*k5;
        o_lo.w = q0*k3 + q3*k0 + q1*k5 - q5*k1 + q2*k6 - q6*k2 - q4*k7 - q7*k4;
        o_hi.x = q0*k4 + q4*k0 + q1*k2 - q2*k1 + q3*k7 + q7*k3 - q5*k6 + q6*k5;
        o_hi.y = q0*k5 + q5*k0 + q1*k3 - q3*k1 - q2*k7 - q7*k2 + q4*k6 - q6*k4;
        o_hi.z = q0*k6 + q6*k0 + q2*k3 - q3*k2 + q1*k7 + q7*k1 - q4*k5 + q5*k4;
        o_hi.w = q0*k7 + q7*k0 + q1*k6 + q6*k1 - q2*k5 - q5*k2 + q3*k4 + q4*k3;

        orow[t * 2 + 0] = o_lo;
        orow[t * 2 + 1] = o_hi;
    }
}

extern "C" void kernel_launch(void* const* d_in, const int* in_sizes, int n_in,
                              void* d_out, int out_size)
{
    const float* x  = (const float*)d_in[0];   // (2, 2048, 8)
    const float* Wq = (const float*)d_in[1];   // (2048, 2048, 4)
    const float* Wk = (const float*)d_in[2];   // (2048, 2048, 4)
    const float* a  = (const float*)d_in[3];   // (3000, 4)
    float* out = (float*)d_out;                // (2, 2048, 2048, 8)

    qk_kernel<<<dim3(S, 2), 256>>>(x, Wq, Wk, a);
    gp_kernel<<<dim3(S, B), 256>>>(out);
}